// round 15
// baseline (speedup 1.0000x reference)
#include <cuda_runtime.h>
#include <cstdint>

#define SS 2048
#define DD 64
#define NH 16
#define NB 2
#define NEGV -1000000000.0f

// ---- fused kernel smem (floats) ----
#define A_QPK 0                     // packed Q: 128 rows x 64 = 8192 floats (32KB)
#define A_DB  8192                  // K+V db: 2 x 4096 floats (16KB tiles)
#define A_MB  16384                 // mask db: 2 x 128 words
#define A_FLOATS 16640              // 66,560 B

// packed scratch: 64 tiles of 2048 floats per bh
__device__ float    g_kpk[(size_t)NB*NH*64*2048];
__device__ float    g_vpk[(size_t)NB*NH*64*2048];
__device__ unsigned g_mbits[(size_t)NB*SS*64];
__device__ float    g_li[(size_t)NB*NH*SS];

#define MMA_BF16(d, a0,a1,a2,a3, b0,b1) \
    asm volatile("mma.sync.aligned.m16n8k16.row.col.f32.bf16.bf16.f32 " \
        "{%0,%1,%2,%3}, {%4,%5,%6,%7}, {%8,%9}, {%0,%1,%2,%3};" \
        : "+f"((d)[0]), "+f"((d)[1]), "+f"((d)[2]), "+f"((d)[3]) \
        : "r"(a0), "r"(a1), "r"(a2), "r"(a3), "r"(b0), "r"(b1))

__device__ __forceinline__ uint32_t bf16pair(float x0, float x1) {
    uint32_t r;
    asm("cvt.rn.bf16x2.f32 %0, %1, %2;" : "=r"(r) : "f"(x1), "f"(x0));
    return r;
}
__device__ __forceinline__ void split_pair(float x0, float x1, uint32_t& hi, uint32_t& lo) {
    hi = bf16pair(x0, x1);
    float h0 = __uint_as_float(hi << 16);
    float h1 = __uint_as_float(hi & 0xffff0000u);
    lo = bf16pair(x0 - h0, x1 - h1);
}
__device__ __forceinline__ uint32_t smem_u32(const void* p) {
    uint32_t a;
    asm("{ .reg .u64 t; cvta.to.shared.u64 t, %1; cvt.u32.u64 %0, t; }" : "=r"(a) : "l"(p));
    return a;
}
// K/Q slot (order {h0,h1,l0,l1}): 64 floats/row, kk 0..3
__device__ __forceinline__ int pk_k(int row, int kk, int tg) {
    return row*64 + ((((kk ^ (row & 3)) << 2) | tg) << 2);
}
// V slot (order {h0,h1,l0,l1}): 32 floats/row, kk 0..1
__device__ __forceinline__ int pk_v(int d, int kk, int tg) {
    return d*32 + ((((kk ^ (d & 1)) << 2) | tg) << 2);
}
__device__ __forceinline__ void cp16(uint32_t dst, const void* src) {
    asm volatile("cp.async.cg.shared.global [%0], [%1], 16;" :: "r"(dst), "l"(src));
}
__device__ __forceinline__ void cp4(uint32_t dst, const void* src) {
    asm volatile("cp.async.ca.shared.global [%0], [%1], 4;" :: "r"(dst), "l"(src));
}
__device__ __forceinline__ void cp_commit() { asm volatile("cp.async.commit_group;"); }
__device__ __forceinline__ void cp_wait0()  { asm volatile("cp.async.wait_group 0;" ::: "memory"); }

// ---------------- prologue kernels ----------------
__global__ void pack_kv_kernel(const float* __restrict__ kg, const float* __restrict__ vg) {
    __shared__ float Vs[32*65];
    const int kt = blockIdx.x & 63;
    const bool isv = blockIdx.x >= 64;
    const int h = blockIdx.y, b = blockIdx.z;
    const int bh = b*NH + h;
    if (!isv) {
        const float* base = kg + ((size_t)bh*SS + kt*32) * DD;
        float* out = g_kpk + ((size_t)bh*64 + kt) * 2048;
        for (int s = threadIdx.x; s < 512; s += 256) {
            int r = s >> 4, kk = (s >> 2) & 3, tg = s & 3;
            int c0 = kk*16 + tg*2;
            const float* kp = base + (size_t)r*DD;
            uint32_t bh0, bl0, bh1, bl1;
            split_pair(kp[c0],   kp[c0+1], bh0, bl0);
            split_pair(kp[c0+8], kp[c0+9], bh1, bl1);
            *reinterpret_cast<uint4*>(out + pk_k(r, kk, tg)) = make_uint4(bh0, bh1, bl0, bl1);
        }
    } else {
        const float* base = vg + ((size_t)bh*SS + kt*32) * DD;
        float* out = g_vpk + ((size_t)bh*64 + kt) * 2048;
        for (int i = threadIdx.x; i < 32*16; i += 256) {
            int k = i >> 4, d4 = (i & 15) << 2;
            float4 v = *reinterpret_cast<const float4*>(base + (size_t)k*DD + d4);
            Vs[k*65 + d4 + 0] = v.x; Vs[k*65 + d4 + 1] = v.y;
            Vs[k*65 + d4 + 2] = v.z; Vs[k*65 + d4 + 3] = v.w;
        }
        __syncthreads();
        for (int s = threadIdx.x; s < 512; s += 256) {
            int d = s >> 3, kk = (s >> 2) & 1, tg = s & 3;
            int c0 = kk*16 + tg*2;
            uint32_t bh0, bl0, bh1, bl1;
            split_pair(Vs[c0*65 + d],     Vs[(c0+1)*65 + d], bh0, bl0);
            split_pair(Vs[(c0+8)*65 + d], Vs[(c0+9)*65 + d], bh1, bl1);
            *reinterpret_cast<uint4*>(out + pk_v(d, kk, tg)) = make_uint4(bh0, bh1, bl0, bl1);
        }
    }
}

__global__ void pack_mask_kernel(const int* __restrict__ maskg) {
    int gt = blockIdx.x*256 + threadIdx.x;
    int widx = gt >> 5;
    int lane = gt & 31;
    int w = widx & 63;
    int row = (widx >> 6) & (SS - 1);
    int b = widx >> 17;
    int c = w*32 + lane;
    unsigned nz = maskg[((size_t)b*SS + row)*SS + c] != 0;
    unsigned bits = __ballot_sync(0xffffffffu, nz);
    if (lane == 0) g_mbits[widx] = bits;
}

// ---------------- fused: scores + attn + l + O (128-row tiles) ----------------
__global__ __launch_bounds__(256, 3)
void sdpa_fused_kernel(const float* __restrict__ qg, float* __restrict__ attng,
                       float* __restrict__ outg)
{
    extern __shared__ float sm[];
    float* Qpk = sm + A_QPK;
    unsigned* maskbuf = reinterpret_cast<unsigned*>(sm + A_MB);
    const uint32_t db_byte = smem_u32(sm + A_DB);
    const uint32_t mb_byte = smem_u32(sm + A_MB);

    const int tid = threadIdx.x;
    const int wid = tid >> 5;
    const int lid = tid & 31;
    const int grp = lid >> 2;
    const int tig = lid & 3;
    const int mrow0 = wid * 16;
    const int g3 = grp & 3;
    const int g1 = grp & 1;

    const int q0 = blockIdx.x * 128;
    const int h  = blockIdx.y;
    const int b  = blockIdx.z;
    const int bh = b*NH + h;

    const float* qbase = qg + ((size_t)bh*SS + q0) * DD;
    float* attnbase = attng + ((size_t)bh*SS + q0) * SS;
    float* outbase  = outg  + ((size_t)bh*SS + q0) * DD;
    const float* kpk = g_kpk + (size_t)bh*64*2048;
    const float* vpk = g_vpk + (size_t)bh*64*2048;
    const unsigned* mbits = g_mbits + ((size_t)b*SS + q0)*64;

    // prefetch K+V tile 0 + mask col 0
    cp16(db_byte + tid*16,              kpk + tid*4);
    cp16(db_byte + (tid+256)*16,        kpk + (tid+256)*4);
    cp16(db_byte + 8192 + tid*16,       vpk + tid*4);
    cp16(db_byte + 8192 + (tid+256)*16, vpk + (tid+256)*4);
    if (tid < 128) cp4(mb_byte + tid*4, mbits + (size_t)tid*64);
    cp_commit();

    // pack Q into smem (pre-scaled by 0.125, exact): 128 rows x 16 slots
    for (int s = tid; s < 2048; s += 256) {
        int row = s >> 4, kk = (s >> 2) & 3, tg = s & 3;
        int c0 = kk*16 + tg*2;
        const float* qp = qbase + (size_t)row*DD;
        uint32_t h0, l0, h1, l1;
        split_pair(qp[c0]*0.125f,   qp[c0+1]*0.125f, h0, l0);
        split_pair(qp[c0+8]*0.125f, qp[c0+9]*0.125f, h1, l1);
        *reinterpret_cast<uint4*>(Qpk + pk_k(row, kk, tg)) = make_uint4(h0, h1, l0, l1);
    }

    const int r0 = mrow0 + grp, r1 = r0 + 8;
    const float* arow0 = Qpk + r0*64 + tig*4;

    float lrun[2] = {0.0f, 0.0f};
    float oacc[8][4];
    #pragma unroll
    for (int n = 0; n < 8; n++) {
        oacc[n][0] = 0.f; oacc[n][1] = 0.f; oacc[n][2] = 0.f; oacc[n][3] = 0.f;
    }

    for (int t = 0; t < 64; t++) {
        cp_wait0();
        __syncthreads();   // copies visible; compute(t-1) done; Qpk ready (t=0)
        if (t < 63) {
            const uint32_t nb = db_byte + ((t+1)&1)*16384;
            const float* kp = kpk + (size_t)(t+1)*2048;
            const float* vp = vpk + (size_t)(t+1)*2048;
            cp16(nb + tid*16,              kp + tid*4);
            cp16(nb + (tid+256)*16,        kp + (tid+256)*4);
            cp16(nb + 8192 + tid*16,       vp + tid*4);
            cp16(nb + 8192 + (tid+256)*16, vp + (tid+256)*4);
            if (tid < 128)
                cp4(mb_byte + ((t+1)&1)*512 + tid*4, mbits + (size_t)tid*64 + (t+1));
            cp_commit();
        }

        const float* kbuf = sm + A_DB + (t&1)*4096;
        const float* vbuf = kbuf + 2048;
        const float* bbase = kbuf + grp*64 + tig*4;

        float acc[4][4];
        #pragma unroll
        for (int n = 0; n < 4; n++) {
            acc[n][0] = 0.f; acc[n][1] = 0.f; acc[n][2] = 0.f; acc[n][3] = 0.f;
        }

        // ---- QK^T ----
        #pragma unroll
        for (int kk = 0; kk < 4; kk++) {
            uint4 qa = *reinterpret_cast<const uint4*>(arow0 + ((kk ^ g3) << 4));
            uint4 qb = *reinterpret_cast<const uint4*>(arow0 + 512 + ((kk ^ g3) << 4));
            const float* bk = bbase + ((kk ^ g3) << 4);
            #pragma unroll
            for (int n = 0; n < 4; n++) {
                uint4 bv = *reinterpret_cast<const uint4*>(bk + n*512);
                MMA_BF16(acc[n], qa.x, qb.x, qa.y, qb.y, bv.x, bv.y);   // hi*hi
                MMA_BF16(acc[n], qa.x, qb.x, qa.y, qb.y, bv.z, bv.w);   // hi*lo
                MMA_BF16(acc[n], qa.z, qb.z, qa.w, qb.w, bv.x, bv.y);   // lo*hi
            }
        }

        // ---- epilogue: mask + attn STG + e = exp(s) + row sums ----
        const unsigned word0 = maskbuf[(t&1)*128 + r0];
        const unsigned word1 = maskbuf[(t&1)*128 + r1];
        float ls0 = 0.0f, ls1 = 0.0f;
        #pragma unroll
        for (int n = 0; n < 4; n++) {
            const int c = n*8 + 2*tig;
            float s0 = acc[n][0] + (((word0 >> c) & 1u) ? 0.0f : NEGV);
            float s1 = acc[n][1] + (((word0 >> (c+1)) & 1u) ? 0.0f : NEGV);
            float s2 = acc[n][2] + (((word1 >> c) & 1u) ? 0.0f : NEGV);
            float s3 = acc[n][3] + (((word1 >> (c+1)) & 1u) ? 0.0f : NEGV);
            const int kcol = t*32 + c;
            *reinterpret_cast<float2*>(attnbase + (size_t)r0*SS + kcol) = make_float2(s0, s1);
            *reinterpret_cast<float2*>(attnbase + (size_t)r1*SS + kcol) = make_float2(s2, s3);
            float e0 = __expf(s0), e1 = __expf(s1), e2 = __expf(s2), e3 = __expf(s3);
            acc[n][0] = e0; acc[n][1] = e1; acc[n][2] = e2; acc[n][3] = e3;
            ls0 += e0 + e1;
            ls1 += e2 + e3;
        }
        lrun[0] += ls0;
        lrun[1] += ls1;

        // ---- PV: e-fragments (already in A-layout) x V tile ----
        #pragma unroll
        for (int kk = 0; kk < 2; kk++) {
            uint32_t ah0, al0, ah1, al1, ah2, al2, ah3, al3;
            split_pair(acc[2*kk][0],   acc[2*kk][1],   ah0, al0);   // r0, k-lo
            split_pair(acc[2*kk][2],   acc[2*kk][3],   ah1, al1);   // r1, k-lo
            split_pair(acc[2*kk+1][0], acc[2*kk+1][1], ah2, al2);   // r0, k-hi
            split_pair(acc[2*kk+1][2], acc[2*kk+1][3], ah3, al3);   // r1, k-hi
            const float* vb = vbuf + grp*32 + tig*4 + ((kk ^ g1) << 4);
            #pragma unroll
            for (int n = 0; n < 8; n++) {
                uint4 bv = *reinterpret_cast<const uint4*>(vb + n*256);
                MMA_BF16(oacc[n], ah0, ah1, ah2, ah3, bv.x, bv.y);   // hi*hi
                MMA_BF16(oacc[n], ah0, ah1, ah2, ah3, bv.z, bv.w);   // hi*lo
                MMA_BF16(oacc[n], al0, al1, al2, al3, bv.x, bv.y);   // lo*hi
            }
        }
    }

    // ---- combine row-sums across the 4 tig lanes (all lanes get result) ----
    #pragma unroll
    for (int hh = 0; hh < 2; hh++) {
        float l = lrun[hh];
        l += __shfl_xor_sync(0xffffffffu, l, 1);
        l += __shfl_xor_sync(0xffffffffu, l, 2);
        lrun[hh] = l;
    }
    const float li0 = 1.0f / lrun[0];
    const float li1 = 1.0f / lrun[1];
    if (tig == 0) {
        float* lib = g_li + (size_t)bh*SS + q0;
        lib[r0] = li0;
        lib[r1] = li1;
    }

    // ---- O = O_unnorm * (1/l) ----
    #pragma unroll
    for (int n = 0; n < 8; n++) {
        const int dcol = n*8 + 2*tig;
        *reinterpret_cast<float2*>(outbase + (size_t)r0*DD + dcol) =
            make_float2(oacc[n][0]*li0, oacc[n][1]*li0);
        *reinterpret_cast<float2*>(outbase + (size_t)r1*DD + dcol) =
            make_float2(oacc[n][2]*li1, oacc[n][3]*li1);
    }
}

// ---------------- prob: streaming exp * (1/l) ----------------
__global__ __launch_bounds__(256)
void prob_kernel(float* __restrict__ probg, const float* __restrict__ attng)
{
    const int row = blockIdx.x;             // 0 .. NB*NH*SS-1
    const float li = g_li[row];
    const float4* a = reinterpret_cast<const float4*>(attng + (size_t)row*SS);
    float4* p = reinterpret_cast<float4*>(probg + (size_t)row*SS);
    #pragma unroll
    for (int j = 0; j < 2; j++) {
        int i = j*256 + threadIdx.x;
        float4 s = a[i];
        float4 pv;
        pv.x = __expf(s.x) * li;
        pv.y = __expf(s.y) * li;
        pv.z = __expf(s.z) * li;
        pv.w = __expf(s.w) * li;
        p[i] = pv;
    }
}

extern "C" void kernel_launch(void* const* d_in, const int* in_sizes, int n_in,
                              void* d_out, int out_size) {
    const float* q    = (const float*)d_in[0];
    const float* k    = (const float*)d_in[1];
    const float* v    = (const float*)d_in[2];
    const int*   mask = (const int*)d_in[3];

    float* out = (float*)d_out;
    const size_t n_out  = (size_t)NB*NH*SS*DD;
    const size_t n_attn = (size_t)NB*NH*SS*SS;
    float* prob = out + n_out;
    float* attn = prob + n_attn;

    dim3 pgrid(128, NH, NB);
    pack_kv_kernel<<<pgrid, 256>>>(k, v);
    pack_mask_kernel<<<(NB*SS*64*32)/256, 256>>>(mask);

    const int smemA = A_FLOATS * (int)sizeof(float);   // 66,560 B
    cudaFuncSetAttribute(sdpa_fused_kernel,
                         cudaFuncAttributeMaxDynamicSharedMemorySize, smemA);
    cudaFuncSetAttribute(sdpa_fused_kernel,
                         cudaFuncAttributePreferredSharedMemoryCarveout, 100);

    dim3 grid(SS/128, NH, NB);   // (16, 16, 2)
    sdpa_fused_kernel<<<grid, 256, smemA>>>(q, attn, out);
    prob_kernel<<<NB*NH*SS, 256>>>(prob, attn);
}

// round 16
// speedup vs baseline: 1.2008x; 1.2008x over previous
#include <cuda_runtime.h>
#include <cstdint>

#define SS 2048
#define DD 64
#define NH 16
#define NB 2
#define NEGV -1000000000.0f

// ---- fused kernel smem (floats) ----
// per buf: K 64-key (4096 fl) @0, V 64-key (4096 fl) @4096 ; two bufs
#define A_DB  0
#define A_MB  16384                 // mask db: 2 x 128 rows x 2 words
#define A_FLOATS 16896              // 67,584 B

// packed scratch: 64 tiles of 2048 floats per bh
__device__ float    g_kpk[(size_t)NB*NH*64*2048];
__device__ float    g_vpk[(size_t)NB*NH*64*2048];
__device__ unsigned g_mbits[(size_t)NB*SS*64];
__device__ float    g_li[(size_t)NB*NH*SS];

#define MMA_BF16(d, a0,a1,a2,a3, b0,b1) \
    asm volatile("mma.sync.aligned.m16n8k16.row.col.f32.bf16.bf16.f32 " \
        "{%0,%1,%2,%3}, {%4,%5,%6,%7}, {%8,%9}, {%0,%1,%2,%3};" \
        : "+f"((d)[0]), "+f"((d)[1]), "+f"((d)[2]), "+f"((d)[3]) \
        : "r"(a0), "r"(a1), "r"(a2), "r"(a3), "r"(b0), "r"(b1))

__device__ __forceinline__ uint32_t bf16pair(float x0, float x1) {
    uint32_t r;
    asm("cvt.rn.bf16x2.f32 %0, %1, %2;" : "=r"(r) : "f"(x1), "f"(x0));
    return r;
}
__device__ __forceinline__ void split_pair(float x0, float x1, uint32_t& hi, uint32_t& lo) {
    hi = bf16pair(x0, x1);
    float h0 = __uint_as_float(hi << 16);
    float h1 = __uint_as_float(hi & 0xffff0000u);
    lo = bf16pair(x0 - h0, x1 - h1);
}
__device__ __forceinline__ uint32_t smem_u32(const void* p) {
    uint32_t a;
    asm("{ .reg .u64 t; cvta.to.shared.u64 t, %1; cvt.u32.u64 %0, t; }" : "=r"(a) : "l"(p));
    return a;
}
// K/Q slot (order {h0,h1,l0,l1}): 64 floats/row, kk 0..3
__device__ __forceinline__ int pk_k(int row, int kk, int tg) {
    return row*64 + ((((kk ^ (row & 3)) << 2) | tg) << 2);
}
// V slot (order {h0,h1,l0,l1}): 32 floats/row, kk 0..1
__device__ __forceinline__ int pk_v(int d, int kk, int tg) {
    return d*32 + ((((kk ^ (d & 1)) << 2) | tg) << 2);
}
__device__ __forceinline__ void cp16(uint32_t dst, const void* src) {
    asm volatile("cp.async.cg.shared.global [%0], [%1], 16;" :: "r"(dst), "l"(src));
}
__device__ __forceinline__ void cp8(uint32_t dst, const void* src) {
    asm volatile("cp.async.ca.shared.global [%0], [%1], 8;" :: "r"(dst), "l"(src));
}
__device__ __forceinline__ void cp_commit() { asm volatile("cp.async.commit_group;"); }
__device__ __forceinline__ void cp_wait0()  { asm volatile("cp.async.wait_group 0;" ::: "memory"); }

// copy one 64-key K+V pair (8192 floats) into a buf: 8 cp16/thread
__device__ __forceinline__ void cp_tile64(uint32_t dst_byte, const float* kp,
                                          const float* vp, int tid) {
    #pragma unroll
    for (int j = 0; j < 4; j++) {
        int e = tid + j*256;
        cp16(dst_byte + e*16, kp + e*4);
        cp16(dst_byte + 16384 + e*16, vp + e*4);
    }
}

// ---------------- prologue kernels ----------------
__global__ void pack_kv_kernel(const float* __restrict__ kg, const float* __restrict__ vg) {
    __shared__ float Vs[32*65];
    const int kt = blockIdx.x & 63;
    const bool isv = blockIdx.x >= 64;
    const int h = blockIdx.y, b = blockIdx.z;
    const int bh = b*NH + h;
    if (!isv) {
        const float* base = kg + ((size_t)bh*SS + kt*32) * DD;
        float* out = g_kpk + ((size_t)bh*64 + kt) * 2048;
        for (int s = threadIdx.x; s < 512; s += 256) {
            int r = s >> 4, kk = (s >> 2) & 3, tg = s & 3;
            int c0 = kk*16 + tg*2;
            const float* kp = base + (size_t)r*DD;
            uint32_t bh0, bl0, bh1, bl1;
            split_pair(kp[c0],   kp[c0+1], bh0, bl0);
            split_pair(kp[c0+8], kp[c0+9], bh1, bl1);
            *reinterpret_cast<uint4*>(out + pk_k(r, kk, tg)) = make_uint4(bh0, bh1, bl0, bl1);
        }
    } else {
        const float* base = vg + ((size_t)bh*SS + kt*32) * DD;
        float* out = g_vpk + ((size_t)bh*64 + kt) * 2048;
        for (int i = threadIdx.x; i < 32*16; i += 256) {
            int k = i >> 4, d4 = (i & 15) << 2;
            float4 v = *reinterpret_cast<const float4*>(base + (size_t)k*DD + d4);
            Vs[k*65 + d4 + 0] = v.x; Vs[k*65 + d4 + 1] = v.y;
            Vs[k*65 + d4 + 2] = v.z; Vs[k*65 + d4 + 3] = v.w;
        }
        __syncthreads();
        for (int s = threadIdx.x; s < 512; s += 256) {
            int d = s >> 3, kk = (s >> 2) & 1, tg = s & 3;
            int c0 = kk*16 + tg*2;
            uint32_t bh0, bl0, bh1, bl1;
            split_pair(Vs[c0*65 + d],     Vs[(c0+1)*65 + d], bh0, bl0);
            split_pair(Vs[(c0+8)*65 + d], Vs[(c0+9)*65 + d], bh1, bl1);
            *reinterpret_cast<uint4*>(out + pk_v(d, kk, tg)) = make_uint4(bh0, bh1, bl0, bl1);
        }
    }
}

__global__ void pack_mask_kernel(const int* __restrict__ maskg) {
    int gt = blockIdx.x*256 + threadIdx.x;
    int widx = gt >> 5;
    int lane = gt & 31;
    int w = widx & 63;
    int row = (widx >> 6) & (SS - 1);
    int b = widx >> 17;
    int c = w*32 + lane;
    unsigned nz = maskg[((size_t)b*SS + row)*SS + c] != 0;
    unsigned bits = __ballot_sync(0xffffffffu, nz);
    if (lane == 0) g_mbits[widx] = bits;
}

// ---------------- fused: scores + attn + l + O (128 rows x 64-key windows) ----------------
__global__ __launch_bounds__(256, 2)
void sdpa_fused_kernel(const float* __restrict__ qg, float* __restrict__ attng,
                       float* __restrict__ outg)
{
    extern __shared__ float sm[];
    unsigned* maskbuf = reinterpret_cast<unsigned*>(sm + A_MB);
    const uint32_t db_byte = smem_u32(sm + A_DB);
    const uint32_t mb_byte = smem_u32(sm + A_MB);

    const int tid = threadIdx.x;
    const int wid = tid >> 5;
    const int lid = tid & 31;
    const int grp = lid >> 2;
    const int tig = lid & 3;
    const int mrow0 = wid * 16;
    const int g3 = grp & 3;
    const int g1 = grp & 1;

    const int q0 = blockIdx.x * 128;
    const int h  = blockIdx.y;
    const int b  = blockIdx.z;
    const int bh = b*NH + h;

    const float* qbase = qg + ((size_t)bh*SS + q0) * DD;
    float* attnbase = attng + ((size_t)bh*SS + q0) * SS;
    float* outbase  = outg  + ((size_t)bh*SS + q0) * DD;
    const float* kpk = g_kpk + (size_t)bh*64*2048;
    const float* vpk = g_vpk + (size_t)bh*64*2048;
    const unsigned* mbits = g_mbits + ((size_t)b*SS + q0)*64;

    // prefetch K+V 64-key window 0 + mask words 0
    cp_tile64(db_byte, kpk, vpk, tid);
    if (tid < 128) cp8(mb_byte + tid*8, mbits + (size_t)tid*64);
    cp_commit();

    // ---- Q fragments resident in registers (pre-scaled by 0.125, exact) ----
    const int r0 = mrow0 + grp, r1 = r0 + 8;
    uint32_t qh[4][4], ql[4][4];
    #pragma unroll
    for (int kk = 0; kk < 4; kk++) {
        const int c0 = kk*16 + 2*tig;
        float2 x00 = *reinterpret_cast<const float2*>(qbase + (size_t)r0*DD + c0);
        float2 x10 = *reinterpret_cast<const float2*>(qbase + (size_t)r1*DD + c0);
        float2 x01 = *reinterpret_cast<const float2*>(qbase + (size_t)r0*DD + c0 + 8);
        float2 x11 = *reinterpret_cast<const float2*>(qbase + (size_t)r1*DD + c0 + 8);
        split_pair(x00.x*0.125f, x00.y*0.125f, qh[kk][0], ql[kk][0]);
        split_pair(x10.x*0.125f, x10.y*0.125f, qh[kk][1], ql[kk][1]);
        split_pair(x01.x*0.125f, x01.y*0.125f, qh[kk][2], ql[kk][2]);
        split_pair(x11.x*0.125f, x11.y*0.125f, qh[kk][3], ql[kk][3]);
    }

    float lrun[2] = {0.0f, 0.0f};
    float oacc[8][4];
    #pragma unroll
    for (int n = 0; n < 8; n++) {
        oacc[n][0] = 0.f; oacc[n][1] = 0.f; oacc[n][2] = 0.f; oacc[n][3] = 0.f;
    }

    for (int t = 0; t < 32; t++) {
        cp_wait0();
        __syncthreads();   // window t visible; compute(t-1) fully done
        if (t < 31) {
            cp_tile64(db_byte + ((t+1)&1)*32768,
                      kpk + (size_t)(t+1)*4096, vpk + (size_t)(t+1)*4096, tid);
            if (tid < 128)
                cp8(mb_byte + ((t+1)&1)*1024 + tid*8, mbits + (size_t)tid*64 + (t+1)*2);
            cp_commit();
        }

        const float* wbuf = sm + A_DB + (t&1)*8192;
        const unsigned* mrow = maskbuf + (t&1)*256;

        #pragma unroll
        for (int c2 = 0; c2 < 2; c2++) {
            const float* kbuf = wbuf + c2*2048;
            const float* vbuf = wbuf + 4096 + c2*2048;
            const float* bbase = kbuf + grp*64 + tig*4;

            float acc[4][4];
            #pragma unroll
            for (int n = 0; n < 4; n++) {
                acc[n][0] = 0.f; acc[n][1] = 0.f; acc[n][2] = 0.f; acc[n][3] = 0.f;
            }

            // ---- QK^T (32 keys) ----
            #pragma unroll
            for (int kk = 0; kk < 4; kk++) {
                const float* bk = bbase + ((kk ^ g3) << 4);
                #pragma unroll
                for (int n = 0; n < 4; n++) {
                    uint4 bv = *reinterpret_cast<const uint4*>(bk + n*512);
                    MMA_BF16(acc[n], qh[kk][0], qh[kk][1], qh[kk][2], qh[kk][3], bv.x, bv.y);
                    MMA_BF16(acc[n], qh[kk][0], qh[kk][1], qh[kk][2], qh[kk][3], bv.z, bv.w);
                    MMA_BF16(acc[n], ql[kk][0], ql[kk][1], ql[kk][2], ql[kk][3], bv.x, bv.y);
                }
            }

            // ---- epilogue: mask + attn STG + e = exp(s) + row sums ----
            const unsigned word0 = mrow[r0*2 + c2];
            const unsigned word1 = mrow[r1*2 + c2];
            float ls0 = 0.0f, ls1 = 0.0f;
            #pragma unroll
            for (int n = 0; n < 4; n++) {
                const int c = n*8 + 2*tig;
                float s0 = acc[n][0] + (((word0 >> c) & 1u) ? 0.0f : NEGV);
                float s1 = acc[n][1] + (((word0 >> (c+1)) & 1u) ? 0.0f : NEGV);
                float s2 = acc[n][2] + (((word1 >> c) & 1u) ? 0.0f : NEGV);
                float s3 = acc[n][3] + (((word1 >> (c+1)) & 1u) ? 0.0f : NEGV);
                const int kcol = t*64 + c2*32 + c;
                *reinterpret_cast<float2*>(attnbase + (size_t)r0*SS + kcol) = make_float2(s0, s1);
                *reinterpret_cast<float2*>(attnbase + (size_t)r1*SS + kcol) = make_float2(s2, s3);
                float e0 = __expf(s0), e1 = __expf(s1), e2 = __expf(s2), e3 = __expf(s3);
                acc[n][0] = e0; acc[n][1] = e1; acc[n][2] = e2; acc[n][3] = e3;
                ls0 += e0 + e1;
                ls1 += e2 + e3;
            }
            lrun[0] += ls0;
            lrun[1] += ls1;

            // ---- PV: e-fragments (already in A-layout) x V chunk ----
            #pragma unroll
            for (int kk = 0; kk < 2; kk++) {
                uint32_t ah0, al0, ah1, al1, ah2, al2, ah3, al3;
                split_pair(acc[2*kk][0],   acc[2*kk][1],   ah0, al0);
                split_pair(acc[2*kk][2],   acc[2*kk][3],   ah1, al1);
                split_pair(acc[2*kk+1][0], acc[2*kk+1][1], ah2, al2);
                split_pair(acc[2*kk+1][2], acc[2*kk+1][3], ah3, al3);
                const float* vb = vbuf + grp*32 + tig*4 + ((kk ^ g1) << 4);
                #pragma unroll
                for (int n = 0; n < 8; n++) {
                    uint4 bv = *reinterpret_cast<const uint4*>(vb + n*256);
                    MMA_BF16(oacc[n], ah0, ah1, ah2, ah3, bv.x, bv.y);
                    MMA_BF16(oacc[n], ah0, ah1, ah2, ah3, bv.z, bv.w);
                    MMA_BF16(oacc[n], al0, al1, al2, al3, bv.x, bv.y);
                }
            }
        }
    }

    // ---- combine row-sums across the 4 tig lanes ----
    #pragma unroll
    for (int hh = 0; hh < 2; hh++) {
        float l = lrun[hh];
        l += __shfl_xor_sync(0xffffffffu, l, 1);
        l += __shfl_xor_sync(0xffffffffu, l, 2);
        lrun[hh] = l;
    }
    const float li0 = 1.0f / lrun[0];
    const float li1 = 1.0f / lrun[1];
    if (tig == 0) {
        float* lib = g_li + (size_t)bh*SS + q0;
        lib[r0] = li0;
        lib[r1] = li1;
    }

    // ---- O = O_unnorm * (1/l) ----
    #pragma unroll
    for (int n = 0; n < 8; n++) {
        const int dcol = n*8 + 2*tig;
        *reinterpret_cast<float2*>(outbase + (size_t)r0*DD + dcol) =
            make_float2(oacc[n][0]*li0, oacc[n][1]*li0);
        *reinterpret_cast<float2*>(outbase + (size_t)r1*DD + dcol) =
            make_float2(oacc[n][2]*li1, oacc[n][3]*li1);
    }
}

// ---------------- prob: streaming exp * (1/l) ----------------
__global__ __launch_bounds__(256)
void prob_kernel(float* __restrict__ probg, const float* __restrict__ attng)
{
    const int row = blockIdx.x;             // 0 .. NB*NH*SS-1
    const float li = g_li[row];
    const float4* a = reinterpret_cast<const float4*>(attng + (size_t)row*SS);
    float4* p = reinterpret_cast<float4*>(probg + (size_t)row*SS);
    #pragma unroll
    for (int j = 0; j < 2; j++) {
        int i = j*256 + threadIdx.x;
        float4 s = a[i];
        float4 pv;
        pv.x = __expf(s.x) * li;
        pv.y = __expf(s.y) * li;
        pv.z = __expf(s.z) * li;
        pv.w = __expf(s.w) * li;
        p[i] = pv;
    }
}

extern "C" void kernel_launch(void* const* d_in, const int* in_sizes, int n_in,
                              void* d_out, int out_size) {
    const float* q    = (const float*)d_in[0];
    const float* k    = (const float*)d_in[1];
    const float* v    = (const float*)d_in[2];
    const int*   mask = (const int*)d_in[3];

    float* out = (float*)d_out;
    const size_t n_out  = (size_t)NB*NH*SS*DD;
    const size_t n_attn = (size_t)NB*NH*SS*SS;
    float* prob = out + n_out;
    float* attn = prob + n_attn;

    dim3 pgrid(128, NH, NB);
    pack_kv_kernel<<<pgrid, 256>>>(k, v);
    pack_mask_kernel<<<(NB*SS*64*32)/256, 256>>>(mask);

    const int smemA = A_FLOATS * (int)sizeof(float);   // 67,584 B
    cudaFuncSetAttribute(sdpa_fused_kernel,
                         cudaFuncAttributeMaxDynamicSharedMemorySize, smemA);
    cudaFuncSetAttribute(sdpa_fused_kernel,
                         cudaFuncAttributePreferredSharedMemoryCarveout, 100);

    dim3 grid(SS/128, NH, NB);   // (16, 16, 2)
    sdpa_fused_kernel<<<grid, 256, smemA>>>(q, attn, out);
    prob_kernel<<<NB*NH*SS, 256>>>(prob, attn);
}